// round 17
// baseline (speedup 1.0000x reference)
#include <cuda_runtime.h>
#include <cuda_bf16.h>
#include <math.h>
#include <stdint.h>

// ---------------- problem constants ----------------
#define BATCH 2
#define C_IN 192
#define C3 576
#define HW 65536
#define IMG 256
#define HEADS 6
#define CH 32
#define WS 8
#define NTOK 64
#define NWIN 2048

// q/k image planes (bf16): (b*384 + ch3) * HW,  ch3 in [0,384)
__device__ __nv_bfloat16 g_qk[(size_t)BATCH * 384 * HW];
// v image planes (fp32): (b*192 + c) * HW
__device__ float g_v[(size_t)BATCH * C_IN * HW];
// window q/k (bf16): ((z*NWIN + win)*HEADS + head)*CH*NTOK ..., z in {0,1}
__device__ __nv_bfloat16 g_wqk[(size_t)2 * NWIN * HEADS * CH * NTOK];
// window v (fp32)
__device__ float g_wv[(size_t)NWIN * HEADS * CH * NTOK];
__device__ float g_att[(size_t)BATCH * C_IN * HW];

// ---------------------------------------------------------------------------
// bf16 helpers (pair-packed b32: low 16 = even, high 16 = odd)
// ---------------------------------------------------------------------------
__device__ __forceinline__ void split2(float e0, float e1, uint32_t& hp, uint32_t& lp)
{
    __nv_bfloat16 h0 = __float2bfloat16(e0);
    __nv_bfloat16 h1 = __float2bfloat16(e1);
    __nv_bfloat16 l0 = __float2bfloat16(e0 - __bfloat162float(h0));
    __nv_bfloat16 l1 = __float2bfloat16(e1 - __bfloat162float(h1));
    __nv_bfloat162 hh; hh.x = h0; hh.y = h1;
    __nv_bfloat162 ll; ll.x = l0; ll.y = l1;
    hp = *reinterpret_cast<uint32_t*>(&hh);
    lp = *reinterpret_cast<uint32_t*>(&ll);
}

__device__ __forceinline__ uint32_t pack_hi(float e0, float e1)
{
    __nv_bfloat162 hh; hh.x = __float2bfloat16(e0); hh.y = __float2bfloat16(e1);
    return *reinterpret_cast<uint32_t*>(&hh);
}

__device__ __forceinline__ void mma16816(float* d, const uint32_t* a, uint32_t b0, uint32_t b1)
{
    asm volatile(
        "mma.sync.aligned.m16n8k16.row.col.f32.bf16.bf16.f32 "
        "{%0,%1,%2,%3}, {%4,%5,%6,%7}, {%8,%9}, {%0,%1,%2,%3};"
        : "+f"(d[0]), "+f"(d[1]), "+f"(d[2]), "+f"(d[3])
        : "r"(a[0]), "r"(a[1]), "r"(a[2]), "r"(a[3]), "r"(b0), "r"(b1));
}

// ---------------------------------------------------------------------------
// K1/K4: GEMM (R10 tiling). CTA 64x256x32, 8 warps 2x4, warp tile 32x64.
// Precision split: q/k tiles (Yb != null, blockIdx.y < 6) use 2 MMA passes,
// hi-only X pack, and write bf16. v tiles / K4 use full 3-pass, write fp32.
// ---------------------------------------------------------------------------
__global__ __launch_bounds__(256, 2) void k_gemm_mma(
    const float* __restrict__ Wt, const float* __restrict__ Xall,
    float* __restrict__ Yf, __nv_bfloat16* __restrict__ Yb,
    const float* __restrict__ bias)
{
    const float* X = Xall + (size_t)blockIdx.z * C_IN * HW;
    const int oTile = blockIdx.y * 64;
    const int pTile = blockIdx.x * 256;
    const bool qk = (Yb != nullptr) && (blockIdx.y < 6);

    __shared__ uint32_t WsH[2][64][9], WsL[2][64][9];
    __shared__ uint32_t XsH[2][256][9], XsL[2][256][9];

    const int tid = threadIdx.x;
    const int lane = tid & 31;
    const int wid = tid >> 5;
    const int warpM = wid >> 2;
    const int warpN = wid & 3;
    const int g = lane >> 2;
    const int t = lane & 3;

    float acc[2][8][4];
#pragma unroll
    for (int im = 0; im < 2; im++)
#pragma unroll
        for (int jn = 0; jn < 8; jn++)
#pragma unroll
            for (int r = 0; r < 4; r++) acc[im][jn][r] = 0.f;

    const int wo = tid >> 2;
    const int wsub = tid & 3;

    for (int k0 = 0; k0 < 192; k0 += 32) {
        {
            const float* wptr = &Wt[(size_t)(oTile + wo) * 192 + k0 + wsub * 8];
            float4 f0 = *(const float4*)wptr;
            float4 f1 = *(const float4*)(wptr + 4);
            float f[8] = {f0.x, f0.y, f0.z, f0.w, f1.x, f1.y, f1.z, f1.w};
#pragma unroll
            for (int j = 0; j < 4; j++) {
                uint32_t hp, lp;
                split2(f[2 * j], f[2 * j + 1], hp, lp);
                int kk2 = wsub * 4 + j;
                int ch = kk2 >> 3, cc = kk2 & 7;
                WsH[ch][wo][cc] = hp;
                WsL[ch][wo][cc] = lp;
            }
        }
        {
#pragma unroll
            for (int it = 0; it < 2; it++) {
                int kp = (tid >> 5) + it * 8;
                int ch = kp >> 3, cc = kp & 7;
                const float* r0 = X + (size_t)(k0 + 2 * kp) * HW + pTile + lane;
#pragma unroll
                for (int pm = 0; pm < 8; pm++) {
                    float f0 = r0[pm * 32];
                    float f1 = r0[pm * 32 + HW];
                    if (!qk) {
                        uint32_t hp, lp;
                        split2(f0, f1, hp, lp);
                        XsH[ch][lane + 32 * pm][cc] = hp;
                        XsL[ch][lane + 32 * pm][cc] = lp;
                    } else {
                        XsH[ch][lane + 32 * pm][cc] = pack_hi(f0, f1);
                    }
                }
            }
        }
        __syncthreads();

#pragma unroll
        for (int ch = 0; ch < 2; ch++) {
            uint32_t Ah[2][4], Al[2][4];
#pragma unroll
            for (int im = 0; im < 2; im++) {
                int r0 = warpM * 32 + im * 16 + g;
                Ah[im][0] = WsH[ch][r0][t];
                Ah[im][1] = WsH[ch][r0 + 8][t];
                Ah[im][2] = WsH[ch][r0][t + 4];
                Ah[im][3] = WsH[ch][r0 + 8][t + 4];
                Al[im][0] = WsL[ch][r0][t];
                Al[im][1] = WsL[ch][r0 + 8][t];
                Al[im][2] = WsL[ch][r0][t + 4];
                Al[im][3] = WsL[ch][r0 + 8][t + 4];
            }
#pragma unroll
            for (int jn = 0; jn < 8; jn++) {
                int col = warpN * 64 + jn * 8 + g;
                uint32_t bh0 = XsH[ch][col][t], bh1 = XsH[ch][col][t + 4];
#pragma unroll
                for (int im = 0; im < 2; im++)
                    mma16816(acc[im][jn], Al[im], bh0, bh1);
                if (!qk) {
                    uint32_t bl0 = XsL[ch][col][t], bl1 = XsL[ch][col][t + 4];
#pragma unroll
                    for (int im = 0; im < 2; im++)
                        mma16816(acc[im][jn], Ah[im], bl0, bl1);
                }
#pragma unroll
                for (int im = 0; im < 2; im++)
                    mma16816(acc[im][jn], Ah[im], bh0, bh1);
            }
        }
        __syncthreads();
    }

    // ---- epilogue ----
    if (qk) {
        __nv_bfloat16* Yq = Yb + (size_t)blockIdx.z * 384 * HW;
#pragma unroll
        for (int im = 0; im < 2; im++) {
            int row = oTile + warpM * 32 + im * 16 + g;
#pragma unroll
            for (int jn = 0; jn < 8; jn++) {
                int col = pTile + warpN * 64 + jn * 8 + t * 2;
                uint32_t p0 = pack_hi(acc[im][jn][0], acc[im][jn][1]);
                uint32_t p1 = pack_hi(acc[im][jn][2], acc[im][jn][3]);
                *(uint32_t*)&Yq[(size_t)row * HW + col] = p0;
                *(uint32_t*)&Yq[(size_t)(row + 8) * HW + col] = p1;
            }
        }
    } else {
        // v rows (K1: row>=384 -> g_v plane row-384) or K4 rows (full M=192)
        const bool isK1 = (Yb != nullptr);
        float* Y = Yf + (size_t)blockIdx.z * C_IN * HW;
        int rowOff = isK1 ? 384 : 0;
#pragma unroll
        for (int im = 0; im < 2; im++) {
            int row = oTile + warpM * 32 + im * 16 + g;
            float bs0 = bias ? bias[row] : 0.f;
            float bs1 = bias ? bias[row + 8] : 0.f;
#pragma unroll
            for (int jn = 0; jn < 8; jn++) {
                int col = pTile + warpN * 64 + jn * 8 + t * 2;
                float2 r0 = make_float2(acc[im][jn][0] + bs0, acc[im][jn][1] + bs0);
                float2 r1 = make_float2(acc[im][jn][2] + bs1, acc[im][jn][3] + bs1);
                *(float2*)&Y[(size_t)(row - rowOff) * HW + col] = r0;
                *(float2*)&Y[(size_t)(row + 8 - rowOff) * HW + col] = r1;
            }
        }
    }
}

// ---------------------------------------------------------------------------
// K2: depthwise 3x3 + window scatter, 8 adjacent pixels per thread.
// q/k planes: bf16 in, bf16 out. v planes: fp32 in/out. fp32 accumulate.
// ---------------------------------------------------------------------------
__global__ __launch_bounds__(256) void k_dwconv(
    const __nv_bfloat16* __restrict__ inQK, const float* __restrict__ inV,
    const float* __restrict__ wd,
    __nv_bfloat16* __restrict__ outQK, float* __restrict__ outV)
{
    const int plane = blockIdx.z;
    const int b = plane / C3, ch3 = plane - b * C3;
    const int x0 = blockIdx.x * 32, y0 = blockIdx.y * 64;
    const int z = ch3 / 192;

    __shared__ float sm[66][36];
    const int tx = threadIdx.x, ty = threadIdx.y;
    const int lt = ty * 32 + tx;

    if (z < 2) {
        const __nv_bfloat16* P = inQK + (size_t)(b * 384 + ch3) * HW;
        for (int e = lt; e < 66 * 36; e += 256) {
            int r = e / 36, cc = e - r * 36;
            int gy = y0 - 1 + r, gx = x0 - 1 + cc;
            float v = 0.f;
            if (gy >= 0 && gy < IMG && gx >= 0 && gx < IMG)
                v = __bfloat162float(P[gy * IMG + gx]);
            sm[r][cc] = v;
        }
    } else {
        const float* P = inV + (size_t)(b * C_IN + (ch3 - 384)) * HW;
        for (int e = lt; e < 66 * 36; e += 256) {
            int r = e / 36, cc = e - r * 36;
            int gy = y0 - 1 + r, gx = x0 - 1 + cc;
            float v = 0.f;
            if (gy >= 0 && gy < IMG && gx >= 0 && gx < IMG) v = P[gy * IMG + gx];
            sm[r][cc] = v;
        }
    }
    __syncthreads();

    const float* wp = wd + ch3 * 9;
    float w[9];
#pragma unroll
    for (int i = 0; i < 9; i++) w[i] = __ldg(wp + i);

    float a[10][3];
#pragma unroll
    for (int r = 0; r < 10; r++)
#pragma unroll
        for (int c2 = 0; c2 < 3; c2++)
            a[r][c2] = sm[ty * 8 + r][tx + c2];

    const int head = (ch3 % 192) >> 5;
    const int c = ch3 & 31;
    const int win = b * 1024 + ((y0 >> 3) + ty) * 32 + (x0 >> 3) + (tx >> 3);
    size_t dstw = (((size_t)win * HEADS + head) * CH + c) * NTOK + (tx & 7);

#pragma unroll
    for (int j = 0; j < 8; j++) {
        float s = w[0] * a[j][0] + w[1] * a[j][1] + w[2] * a[j][2]
                + w[3] * a[j + 1][0] + w[4] * a[j + 1][1] + w[5] * a[j + 1][2]
                + w[6] * a[j + 2][0] + w[7] * a[j + 2][1] + w[8] * a[j + 2][2];
        if (z < 2)
            outQK[(size_t)z * NWIN * HEADS * CH * NTOK + dstw + 8 * j] = __float2bfloat16(s);
        else
            outV[dstw + 8 * j] = s;
    }
}

// ---------------------------------------------------------------------------
// K3: one block per window, 8 warps, loops 6 heads; q/k loaded as bf16.
// ---------------------------------------------------------------------------
#define SMA_MWH 0
#define SMA_MWL 8448
#define SMA_QH 16896
#define SMA_KH 21120
#define SMA_VPH 25344
#define SMA_VPL 29568
#define SMA_VTH 33792
#define SMA_VTL 38144
#define SMA_VS  42496
#define SMA_AS  42496
#define SMA_AH  51200
#define SMA_AL  53376
#define SMA_MBS 55552
#define SMA_TOTAL 55808

__global__ __launch_bounds__(256) void k_attn(
    const __nv_bfloat16* __restrict__ wqk, const float* __restrict__ wv,
    const float* __restrict__ temperature,
    const float* __restrict__ mlp_w, const float* __restrict__ mlp_b,
    float* __restrict__ out)
{
    extern __shared__ char smraw[];
    uint32_t* mwh = (uint32_t*)(smraw + SMA_MWH);
    uint32_t* mwl = (uint32_t*)(smraw + SMA_MWL);
    uint32_t* qh  = (uint32_t*)(smraw + SMA_QH);
    uint32_t* kh  = (uint32_t*)(smraw + SMA_KH);
    uint32_t* vph = (uint32_t*)(smraw + SMA_VPH);
    uint32_t* vpl = (uint32_t*)(smraw + SMA_VPL);
    uint32_t* vth = (uint32_t*)(smraw + SMA_VTH);
    uint32_t* vtl = (uint32_t*)(smraw + SMA_VTL);
    float*    vsf = (float*)(smraw + SMA_VS);
    float*    As  = (float*)(smraw + SMA_AS);
    uint32_t* Ahs = (uint32_t*)(smraw + SMA_AH);
    uint32_t* Als = (uint32_t*)(smraw + SMA_AL);
    float*    mbs = (float*)(smraw + SMA_MBS);

    const int winId = blockIdx.x;
    const int tid = threadIdx.x;
    const int lane = tid & 31;
    const int wid = tid >> 5;
    const int g = lane >> 2;
    const int t = lane & 3;
    const int mi = wid >> 2;
    const int ni = wid & 3;

    const size_t zqk = (size_t)NWIN * HEADS * CH * NTOK;

    {
        int y = tid >> 2, pp0 = (tid & 3) * 8;
        const float* p = mlp_w + y * 64 + pp0 * 2;
        float4 f0 = *(const float4*)p;
        float4 f1 = *(const float4*)(p + 4);
        float4 f2 = *(const float4*)(p + 8);
        float4 f3 = *(const float4*)(p + 12);
        float f[16] = {f0.x, f0.y, f0.z, f0.w, f1.x, f1.y, f1.z, f1.w,
                       f2.x, f2.y, f2.z, f2.w, f3.x, f3.y, f3.z, f3.w};
#pragma unroll
        for (int i = 0; i < 8; i++) {
            uint32_t hp, lp;
            split2(f[2 * i], f[2 * i + 1], hp, lp);
            mwh[y * 33 + pp0 + i] = hp;
            mwl[y * 33 + pp0 + i] = lp;
        }
    }
    if (tid < 64) mbs[tid] = mlp_b[tid];

    const int rr = tid >> 3;
    const int seg = tid & 7;

    const int bb = winId >> 10, rem = winId & 1023;
    const int h1 = rem >> 5, w1 = rem & 31;

    // prefetch regs: q/k as 4x bf16x2 words, v as 8 floats
    uint32_t q4[4], k4[4];
    float fv[8];
    {
        const size_t hb = (size_t)(winId * HEADS) * (CH * NTOK) + rr * 64 + seg * 8;
        *(uint4*)q4 = *(const uint4*)(wqk + hb);
        *(uint4*)k4 = *(const uint4*)(wqk + zqk + hb);
        const float* pv = wv + hb;
        float4 a = *(const float4*)pv;
        float4 b = *(const float4*)(pv + 4);
        fv[0]=a.x; fv[1]=a.y; fv[2]=a.z; fv[3]=a.w; fv[4]=b.x; fv[5]=b.y; fv[6]=b.z; fv[7]=b.w;
    }

    for (int head = 0; head < HEADS; head++) {
        __syncthreads();

        // ---- q: decode, norm, hi-pack ----
        {
            float f[8];
#pragma unroll
            for (int i = 0; i < 4; i++) {
                __nv_bfloat162 p2 = *reinterpret_cast<__nv_bfloat162*>(&q4[i]);
                f[2 * i] = __bfloat162float(p2.x);
                f[2 * i + 1] = __bfloat162float(p2.y);
            }
            float ss = 0.f;
#pragma unroll
            for (int i = 0; i < 8; i++) ss += f[i] * f[i];
            ss += __shfl_xor_sync(0xffffffffu, ss, 1);
            ss += __shfl_xor_sync(0xffffffffu, ss, 2);
            ss += __shfl_xor_sync(0xffffffffu, ss, 4);
            float inv = 1.0f / fmaxf(sqrtf(ss), 1e-12f);
#pragma unroll
            for (int i = 0; i < 4; i++)
                qh[rr * 33 + seg * 4 + i] = pack_hi(f[2 * i] * inv, f[2 * i + 1] * inv);
        }
        // ---- k: decode, norm, hi-pack ----
        {
            float f[8];
#pragma unroll
            for (int i = 0; i < 4; i++) {
                __nv_bfloat162 p2 = *reinterpret_cast<__nv_bfloat162*>(&k4[i]);
                f[2 * i] = __bfloat162float(p2.x);
                f[2 * i + 1] = __bfloat162float(p2.y);
            }
            float ss = 0.f;
#pragma unroll
            for (int i = 0; i < 8; i++) ss += f[i] * f[i];
            ss += __shfl_xor_sync(0xffffffffu, ss, 1);
            ss += __shfl_xor_sync(0xffffffffu, ss, 2);
            ss += __shfl_xor_sync(0xffffffffu, ss, 4);
            float inv = 1.0f / fmaxf(sqrtf(ss), 1e-12f);
#pragma unroll
            for (int i = 0; i < 4; i++)
                kh[rr * 33 + seg * 4 + i] = pack_hi(f[2 * i] * inv, f[2 * i + 1] * inv);
        }
        // ---- v: split-pack + fp32 stage ----
        {
#pragma unroll
            for (int i = 0; i < 4; i++) {
                uint32_t hp, lp;
                split2(fv[2 * i], fv[2 * i + 1], hp, lp);
                vph[rr * 33 + seg * 4 + i] = hp;
                vpl[rr * 33 + seg * 4 + i] = lp;
            }
            *(float4*)&vsf[rr * 68 + seg * 8] = make_float4(fv[0], fv[1], fv[2], fv[3]);
            *(float4*)&vsf[rr * 68 + seg * 8 + 4] = make_float4(fv[4], fv[5], fv[6], fv[7]);
        }
        // ---- prefetch next head ----
        if (head + 1 < HEADS) {
            const size_t hb = (size_t)(winId * HEADS + head + 1) * (CH * NTOK) + rr * 64 + seg * 8;
            *(uint4*)q4 = *(const uint4*)(wqk + hb);
            *(uint4*)k4 = *(const uint4*)(wqk + zqk + hb);
            const float* pv = wv + hb;
            float4 a = *(const float4*)pv;
            float4 b = *(const float4*)(pv + 4);
            fv[0]=a.x; fv[1]=a.y; fv[2]=a.z; fv[3]=a.w; fv[4]=b.x; fv[5]=b.y; fv[6]=b.z; fv[7]=b.w;
        }
        __syncthreads();

        // ---- build v^T pairs over d ----
        {
            int x = tid >> 2;
            int dpb = tid & 3;
#pragma unroll
            for (int i = 0; i < 4; i++) {
                int dp = dpb + 4 * i;
                float e0 = vsf[(2 * dp) * 68 + x];
                float e1 = vsf[(2 * dp + 1) * 68 + x];
                uint32_t hp, lp;
                split2(e0, e1, hp, lp);
                vth[x * 17 + dp] = hp;
                vtl[x * 17 + dp] = lp;
            }
        }
        __syncthreads();

        // ---- QK^T (hi-only) ----
        {
            float cacc[4] = {0.f, 0.f, 0.f, 0.f};
#pragma unroll
            for (int c = 0; c < 4; c++) {
                int p0 = c * 8 + t, p1 = p0 + 4;
                uint32_t A[4];
                A[0] = qh[(mi * 16 + g) * 33 + p0];
                A[1] = qh[(mi * 16 + g + 8) * 33 + p0];
                A[2] = qh[(mi * 16 + g) * 33 + p1];
                A[3] = qh[(mi * 16 + g + 8) * 33 + p1];
                uint32_t b0 = kh[(ni * 8 + g) * 33 + p0];
                uint32_t b1 = kh[(ni * 8 + g) * 33 + p1];
                mma16816(cacc, A, b0, b1);
            }
            const float temp = temperature[head];
            As[(mi * 16 + g) * 36 + ni * 8 + 2 * t] = cacc[0] * temp;
            As[(mi * 16 + g) * 36 + ni * 8 + 2 * t + 1] = cacc[1] * temp;
            As[(mi * 16 + g + 8) * 36 + ni * 8 + 2 * t] = cacc[2] * temp;
            As[(mi * 16 + g + 8) * 36 + ni * 8 + 2 * t + 1] = cacc[3] * temp;
        }
        __syncthreads();

        // ---- softmax; emit split pairs ----
        {
            int r = tid >> 3, j0 = (tid & 7) * 4;
            float4 v4 = *(const float4*)&As[r * 36 + j0];
            float v[4] = {v4.x, v4.y, v4.z, v4.w};
            float m = fmaxf(fmaxf(v[0], v[1]), fmaxf(v[2], v[3]));
            m = fmaxf(m, __shfl_xor_sync(0xffffffffu, m, 1));
            m = fmaxf(m, __shfl_xor_sync(0xffffffffu, m, 2));
            m = fmaxf(m, __shfl_xor_sync(0xffffffffu, m, 4));
            float s = 0.f;
#pragma unroll
            for (int i = 0; i < 4; i++) { v[i] = __expf(v[i] - m); s += v[i]; }
            s += __shfl_xor_sync(0xffffffffu, s, 1);
            s += __shfl_xor_sync(0xffffffffu, s, 2);
            s += __shfl_xor_sync(0xffffffffu, s, 4);
            float inv = 1.0f / s;
            int jp = (tid & 7) * 2;
            uint32_t hp, lp;
            split2(v[0] * inv, v[1] * inv, hp, lp);
            Ahs[r * 17 + jp] = hp; Als[r * 17 + jp] = lp;
            split2(v[2] * inv, v[3] * inv, hp, lp);
            Ahs[r * 17 + jp + 1] = hp; Als[r * 17 + jp + 1] = lp;
        }
        __syncthreads();

        // ---- A·V and V·mlp_w^T; fused epilogue ----
        {
            float oa[2][4], ga[2][4];
#pragma unroll
            for (int nt = 0; nt < 2; nt++)
#pragma unroll
                for (int r = 0; r < 4; r++) { oa[nt][r] = 0.f; ga[nt][r] = 0.f; }

#pragma unroll
            for (int c = 0; c < 2; c++) {
                int p0 = c * 8 + t, p1 = p0 + 4;
                uint32_t Ahf[4], Alf[4];
                Ahf[0] = Ahs[(mi * 16 + g) * 17 + p0];
                Ahf[1] = Ahs[(mi * 16 + g + 8) * 17 + p0];
                Ahf[2] = Ahs[(mi * 16 + g) * 17 + p1];
                Ahf[3] = Ahs[(mi * 16 + g + 8) * 17 + p1];
                Alf[0] = Als[(mi * 16 + g) * 17 + p0];
                Alf[1] = Als[(mi * 16 + g + 8) * 17 + p0];
                Alf[2] = Als[(mi * 16 + g) * 17 + p1];
                Alf[3] = Als[(mi * 16 + g + 8) * 17 + p1];
#pragma unroll
                for (int nt = 0; nt < 2; nt++) {
                    int n = (ni * 2 + nt) * 8 + g;
                    uint32_t bh0 = vth[n * 17 + p0], bh1 = vth[n * 17 + p1];
                    uint32_t bl0 = vtl[n * 17 + p0], bl1 = vtl[n * 17 + p1];
                    mma16816(oa[nt], Ahf, bl0, bl1);
                    mma16816(oa[nt], Alf, bh0, bh1);
                    mma16816(oa[nt], Ahf, bh0, bh1);
                }
            }
#pragma unroll
            for (int c = 0; c < 4; c++) {
                int p0 = c * 8 + t, p1 = p0 + 4;
                uint32_t Vh[4], Vl[4];
                Vh[0] = vph[(mi * 16 + g) * 33 + p0];
                Vh[1] = vph[(mi * 16 + g + 8) * 33 + p0];
                Vh[2] = vph[(mi * 16 + g) * 33 + p1];
                Vh[3] = vph[(mi * 16 + g + 8) * 33 + p1];
                Vl[0] = vpl[(mi * 16 + g) * 33 + p0];
                Vl[1] = vpl[(mi * 16 + g + 8) * 33 + p0];
                Vl[2] = vpl[(mi * 16 + g) * 33 + p1];
                Vl[3] = vpl[(mi * 16 + g + 8) * 33 + p1];
#pragma unroll
                for (int nt = 0; nt < 2; nt++) {
                    int n = (ni * 2 + nt) * 8 + g;
                    uint32_t bh0 = mwh[n * 33 + p0], bh1 = mwh[n * 33 + p1];
                    uint32_t bl0 = mwl[n * 33 + p0], bl1 = mwl[n * 33 + p1];
                    mma16816(ga[nt], Vh, bl0, bl1);
                    mma16816(ga[nt], Vl, bh0, bh1);
                    mma16816(ga[nt], Vh, bh0, bh1);
                }
            }
#pragma unroll
            for (int nt = 0; nt < 2; nt++) {
                int ntok = ni * 2 + nt;
                float b0 = mbs[ntok * 8 + 2 * t];
                float b1 = mbs[ntok * 8 + 2 * t + 1];
#pragma unroll
                for (int half = 0; half < 2; half++) {
                    int row = mi * 16 + g + half * 8;
                    float o0 = oa[nt][half * 2], o1 = oa[nt][half * 2 + 1];
                    float x0 = ga[nt][half * 2] + b0;
                    float x1 = ga[nt][half * 2 + 1] + b1;
                    float ge0 = 0.5f * x0 * (1.0f + erff(x0 * 0.70710678118654752f));
                    float ge1 = 0.5f * x1 * (1.0f + erff(x1 * 0.70710678118654752f));
                    size_t addr = ((((size_t)bb * C_IN + head * CH + row) * IMG
                                    + h1 * 8 + ntok) * IMG) + w1 * 8 + 2 * t;
                    *(float2*)&out[addr] = make_float2(o0 * ge0, o1 * ge1);
                }
            }
        }
    }
}

// ---------------------------------------------------------------------------
extern "C" void kernel_launch(void* const* d_in, const int* in_sizes, int n_in,
                              void* d_out, int out_size)
{
    const float* x           = (const float*)d_in[0];
    const float* w_qkv       = (const float*)d_in[1];
    const float* w_dw        = (const float*)d_in[2];
    const float* temperature = (const float*)d_in[3];
    const float* mlp_w       = (const float*)d_in[4];
    const float* mlp_b       = (const float*)d_in[5];
    const float* proj_w      = (const float*)d_in[6];
    const float* proj_b      = (const float*)d_in[7];
    float* out = (float*)d_out;

    __nv_bfloat16 *qk, *wqk;
    float *v, *wv, *att;
    cudaGetSymbolAddress((void**)&qk, g_qk);
    cudaGetSymbolAddress((void**)&v, g_v);
    cudaGetSymbolAddress((void**)&wqk, g_wqk);
    cudaGetSymbolAddress((void**)&wv, g_wv);
    cudaGetSymbolAddress((void**)&att, g_att);

    cudaFuncSetAttribute(k_attn, cudaFuncAttributeMaxDynamicSharedMemorySize, SMA_TOTAL);

    // K1: qkv projection (q,k -> bf16 planes; v -> fp32 planes)
    k_gemm_mma<<<dim3(HW / 256, C3 / 64, BATCH), 256>>>(w_qkv, x, v, qk, nullptr);
    // K2: depthwise + window scatter
    k_dwconv<<<dim3(IMG / 32, IMG / 64, BATCH * C3), dim3(32, 8)>>>(qk, v, w_dw, wqk, wv);
    // K3: attention
    k_attn<<<NWIN, 256, SMA_TOTAL>>>(wqk, wv, temperature, mlp_w, mlp_b, att);
    // K4: output projection (fp32, bias)
    k_gemm_mma<<<dim3(HW / 256, C_IN / 64, BATCH), 256>>>(proj_w, att, out, nullptr, proj_b);
}